// round 7
// baseline (speedup 1.0000x reference)
#include <cuda_runtime.h>
#include <cstdint>

// Zero-initialized at module load; self-reset by the finalizing block each run.
__device__ unsigned int g_conf[25];
__device__ unsigned int g_done;

#define THREADS 256

// Fast soft-argmax class prediction.
// No max-subtraction: logits are O(10) at most; __expf is safe in fp32.
// round(dot/s) replaced by boundary compares (s > 0 always):
//   p = #{ k in 0..3 : dot > (k+0.5)*s }
__device__ __forceinline__ int pred5(float x0, float x1, float x2, float x3, float x4) {
    float e0 = __expf(x0);
    float e1 = __expf(x1);
    float e2 = __expf(x2);
    float e3 = __expf(x3);
    float e4 = __expf(x4);
    float s   = ((e0 + e1) + (e2 + e3)) + e4;
    float dot = e1 + 2.0f * e2 + (3.0f * e3 + 4.0f * e4);
    int p = 0;
    p += (dot > 0.5f * s);
    p += (dot > 1.5f * s);
    p += (dot > 2.5f * s);
    p += (dot > 3.5f * s);
    return p;
}

__device__ __forceinline__ void warp_agg_add(unsigned int* sconf, int flat, int lane) {
    unsigned int am   = __activemask();
    unsigned int mask = __match_any_sync(am, flat);
    int leader = __ffs(mask) - 1;
    if (lane == leader) atomicAdd(&sconf[flat], (unsigned int)__popc(mask));
}

__global__ void __launch_bounds__(THREADS, 4)
kappa_direct_kernel(const float* __restrict__ preds,
                    const int* __restrict__ labels,
                    float* __restrict__ out,
                    int n) {
    __shared__ unsigned int sconf[25];
    __shared__ unsigned int s_is_last;

    const int tid  = threadIdx.x;
    const int lane = tid & 31;
    if (tid < 25) sconf[tid] = 0u;
    __syncthreads();

    const int groups = n >> 2;                 // 4 rows per group (5 float4 + 1 int4)
    const int stride = gridDim.x * blockDim.x;
    const float4* __restrict__ p4 = reinterpret_cast<const float4*>(preds);
    const int4*   __restrict__ t4 = reinterpret_cast<const int4*>(labels);

    for (int g = blockIdx.x * blockDim.x + tid; g < groups; g += stride) {
        const float4* r = p4 + (size_t)g * 5;
        float4 a  = r[0];
        float4 b4 = r[1];
        float4 c  = r[2];
        float4 d  = r[3];
        float4 e  = r[4];
        int4   t  = t4[g];

        int p0 = pred5(a.x,  a.y,  a.z,  a.w,  b4.x);
        int p1 = pred5(b4.y, b4.z, b4.w, c.x,  c.y);
        int p2 = pred5(c.z,  c.w,  d.x,  d.y,  d.z);
        int p3 = pred5(d.w,  e.x,  e.y,  e.z,  e.w);

        warp_agg_add(sconf, t.x * 5 + p0, lane);
        warp_agg_add(sconf, t.y * 5 + p1, lane);
        warp_agg_add(sconf, t.z * 5 + p2, lane);
        warp_agg_add(sconf, t.w * 5 + p3, lane);
    }

    __syncthreads();
    // Flush block-local counts to global.
    if (tid < 25) {
        unsigned int v = sconf[tid];
        if (v) atomicAdd(&g_conf[tid], v);
    }
    __threadfence();
    __syncthreads();

    // Last block to finish runs the epilogue and self-resets the globals.
    if (tid == 0)
        s_is_last = (atomicAdd(&g_done, 1u) == gridDim.x - 1u) ? 1u : 0u;
    __syncthreads();

    if (s_is_last && tid == 0) {
        __threadfence();
        double cf[25];
        #pragma unroll
        for (int i = 0; i < 25; ++i) {
            cf[i] = (double)(*(volatile unsigned int*)&g_conf[i]);
            g_conf[i] = 0u;                    // reset for next graph replay
        }
        g_done = 0u;

        // Tail rows (n % 4), at most 3, handled serially.
        for (int i = (groups << 2); i < n; ++i) {
            const float* rr = preds + (size_t)i * 5;
            int p = pred5(rr[0], rr[1], rr[2], rr[3], rr[4]);
            cf[labels[i] * 5 + p] += 1.0;
        }

        double th[5] = {0, 0, 0, 0, 0}, ph[5] = {0, 0, 0, 0, 0};
        #pragma unroll
        for (int i = 0; i < 5; ++i)
            #pragma unroll
            for (int j = 0; j < 5; ++j) {
                th[i] += cf[i * 5 + j];
                ph[j] += cf[i * 5 + j];
            }
        double num = 0.0, den = 0.0;
        #pragma unroll
        for (int i = 0; i < 5; ++i)
            #pragma unroll
            for (int j = 0; j < 5; ++j) {
                double w = (double)((i - j) * (i - j)) * (1.0 / 16.0);
                num += cf[i * 5 + j] * w;
                den += th[i] * ph[j] * w;
            }
        // (num/N) / (den/N^2) = num * N / den
        out[0] = (float)(num * (double)n / den);
    }
}

extern "C" void kernel_launch(void* const* d_in, const int* in_sizes, int n_in,
                              void* d_out, int out_size) {
    const float* preds  = (const float*)d_in[0];
    const int*   labels = (const int*)d_in[1];
    const int n = in_sizes[1];

    const int groups = n >> 2;
    int blocks = 148 * 4;                      // one resident wave at 4 blocks/SM
    int needed = (groups + THREADS - 1) / THREADS;
    if (blocks > needed) blocks = needed;
    if (blocks < 1) blocks = 1;

    kappa_direct_kernel<<<blocks, THREADS>>>(preds, labels, (float*)d_out, n);
}